// round 7
// baseline (speedup 1.0000x reference)
#include <cuda_runtime.h>
#include <cuda_bf16.h>
#include <cstdint>

// FSQ: q = round(4*tanh( W @ LayerNorm(x) )), folded into a single pass:
//   logit_n = rstd * (dot(x, gamma*W_n) - mu * s_n) + b_n
// R7: K-split warp pairs. Two warps share 4 rows; each covers half of K for
// all 8 levels with f32x2 accumulators (32 regs). Partials combined via smem.
// ~78 regs -> 3 blocks/SM (24 warps). x via LDG.64 double-buffered, W' in
// smem as u64 per (pair,level), stride 9 -> conflict-free LDS.64.

typedef unsigned long long u64;

__device__ __forceinline__ void fma2(u64 &d, u64 a, u64 b) {
    asm("fma.rn.f32x2 %0, %1, %2, %0;" : "+l"(d) : "l"(a), "l"(b));
}
__device__ __forceinline__ void add2(u64 &d, u64 a) {
    asm("add.rn.f32x2 %0, %0, %1;" : "+l"(d) : "l"(a));
}
__device__ __forceinline__ u64 pack2(float a, float b) {
    u64 r;
    asm("mov.b64 %0, {%1, %2};" : "=l"(r) : "r"(__float_as_uint(a)), "r"(__float_as_uint(b)));
    return r;
}
__device__ __forceinline__ float2 up2(u64 v) {
    unsigned a, b;
    asm("mov.b64 {%0, %1}, %2;" : "=r"(a), "=r"(b) : "l"(v));
    return make_float2(__uint_as_float(a), __uint_as_float(b));
}
__device__ __forceinline__ float pairsum(u64 v) {
    float2 f = up2(v);
    return f.x + f.y;
}

// rintf(4*tanh(x)), fast-math-proof (fmaf/rcp.rn/sqrt.rn only).
__device__ __forceinline__ float tanh4_round(float x) {
    float ax = fabsf(x);
    float r;
    if (ax >= 1.5f) {
        r = 4.0f;   // 4*tanh(1.5)=3.6206 -> 4; monotone beyond
    } else {
        const float T2L = 2.8853900817779268f;   // 2*log2(e)
        float t = ax * T2L;
        float k = rintf(t);
        float f = t - k;
        float y = f * 0.6931471805599453f;
        float p = 1.9841269841e-4f;
        p = fmaf(p, y, 1.3888888888e-3f);
        p = fmaf(p, y, 8.3333333333e-3f);
        p = fmaf(p, y, 4.1666666667e-2f);
        p = fmaf(p, y, 1.6666666667e-1f);
        p = fmaf(p, y, 0.5f);
        p = fmaf(p, y, 1.0f);
        p = fmaf(p, y, 1.0f);
        float scale = __int_as_float(((int)k + 127) << 23);
        float e = p * scale;                     // exp(2*ax)
        float th = (e - 1.0f) * __frcp_rn(e + 1.0f);
        r = rintf(4.0f * th);
    }
    return copysignf(r, x);
}

static const int D       = 1024;
static const int PAIRS   = 512;   // f32x2 pairs per row
static const int NL      = 8;
static const int WPAD    = 9;     // u64 entries per pair (8 levels + 1 pad)
static const int R       = 4;     // rows per warp-pair
static const int ROWS_PB = 16;    // 4 groups x 4 rows (8 warps = 4 K-split pairs)

__global__ void __launch_bounds__(256, 3)
fsq_kernel(const float* __restrict__ x, const float* __restrict__ gamma,
           const float* __restrict__ beta, const float* __restrict__ W,
           float* __restrict__ out, int rows)
{
    __shared__ u64   sW[PAIRS * WPAD];       // 36864 B: W'[pair][level] f32x2
    __shared__ float sPart[2][ROWS_PB][10];  // [khalf][row][sum,ssq,8 dots]
    __shared__ float sRed[8][16];
    __shared__ float sSB[16];                // s[0..7], b[0..7]

    const int tid   = threadIdx.x;
    const int lane  = tid & 31;
    const int wid   = tid >> 5;
    const int grp   = wid >> 1;      // row group 0..3
    const int khalf = wid & 1;       // K half 0..1

    // ---------------- prep: W' = gamma*W into smem; s_n, b_n ----------------
    float sP[NL], bP[NL];
#pragma unroll
    for (int n = 0; n < NL; n++) { sP[n] = 0.0f; bP[n] = 0.0f; }
    {
        const u64* g2 = (const u64*)gamma;  // [512]
        const u64* e2 = (const u64*)beta;
        const u64* W2 = (const u64*)W;      // [8][512]
#pragma unroll
        for (int i = 0; i < 2; i++) {
            int p = tid + i * 256;
            float2 g = up2(g2[p]);
            float2 b = up2(e2[p]);
#pragma unroll
            for (int n = 0; n < NL; n++) {
                float2 w = up2(W2[n * PAIRS + p]);
                float pl = g.x * w.x;
                float ph = g.y * w.y;
                sW[p * WPAD + n] = pack2(pl, ph);
                sP[n] += pl + ph;
                bP[n] += b.x * w.x + b.y * w.y;
            }
        }
    }
#pragma unroll
    for (int o = 16; o; o >>= 1) {
#pragma unroll
        for (int n = 0; n < NL; n++) {
            sP[n] += __shfl_xor_sync(0xffffffffu, sP[n], o);
            bP[n] += __shfl_xor_sync(0xffffffffu, bP[n], o);
        }
    }
    if (lane == 0) {
#pragma unroll
        for (int n = 0; n < NL; n++) {
            sRed[wid][n]     = sP[n];
            sRed[wid][8 + n] = bP[n];
        }
    }
    __syncthreads();
    if (tid < 16) {
        float v = 0.0f;
#pragma unroll
        for (int w = 0; w < 8; w++) v += sRed[w][tid];
        sSB[tid] = v;
    }
    __syncthreads();

    // ---------------- main: 4 rows, half-K per warp ----------------
    int rowBase = blockIdx.x * ROWS_PB + grp * R;
    if (rowBase + R > rows) rowBase = rows - R;   // safety (exact at 65536)
    if (rowBase < 0) rowBase = 0;

    // base pointer at this warp's K-half start; offsets are immediates
    const u64* bp = (const u64*)x + (size_t)rowBase * PAIRS + khalf * 256 + lane;

    u64 dots[R][NL];
    u64 sum2[R], ssq2[R];
#pragma unroll
    for (int r = 0; r < R; r++) {
        sum2[r] = 0ull; ssq2[r] = 0ull;
#pragma unroll
        for (int n = 0; n < NL; n++) dots[r][n] = 0ull;
    }

    u64 c[R];
#pragma unroll
    for (int r = 0; r < R; r++) c[r] = __ldcs(bp + r * PAIRS);

#pragma unroll
    for (int it = 0; it < 8; it++) {
        u64 nx[R];
        if (it < 7) {
#pragma unroll
            for (int r = 0; r < R; r++)
                nx[r] = __ldcs(bp + r * PAIRS + (it + 1) * 32);
        }
        // stats (f32x2)
#pragma unroll
        for (int r = 0; r < R; r++) {
            add2(sum2[r], c[r]);
            fma2(ssq2[r], c[r], c[r]);
        }
        // dots: one W entry per level serves 4 rows
        const u64* wrow = &sW[(khalf * 256 + it * 32 + lane) * WPAD];
#pragma unroll
        for (int n = 0; n < NL; n++) {
            u64 w = wrow[n];
#pragma unroll
            for (int r = 0; r < R; r++) fma2(dots[r][n], c[r], w);
        }
#pragma unroll
        for (int r = 0; r < R; r++) c[r] = nx[r];
    }

    // ---------------- warp reduce + stash partials ----------------
#pragma unroll
    for (int r = 0; r < R; r++) {
        float s = pairsum(sum2[r]);
        float q = pairsum(ssq2[r]);
        float dv[NL];
#pragma unroll
        for (int n = 0; n < NL; n++) dv[n] = pairsum(dots[r][n]);
#pragma unroll
        for (int o = 16; o; o >>= 1) {
            s += __shfl_xor_sync(0xffffffffu, s, o);
            q += __shfl_xor_sync(0xffffffffu, q, o);
#pragma unroll
            for (int n = 0; n < NL; n++)
                dv[n] += __shfl_xor_sync(0xffffffffu, dv[n], o);
        }
        if (lane == 0) {
            int rr = grp * R + r;
            sPart[khalf][rr][0] = s;
            sPart[khalf][rr][1] = q;
#pragma unroll
            for (int n = 0; n < NL; n++) sPart[khalf][rr][2 + n] = dv[n];
        }
    }
    __syncthreads();

    // ---------------- tail: 128 threads = 16 rows x 8 levels ----------------
    if (tid < ROWS_PB * NL) {
        int rr = tid >> 3;
        int n  = tid & 7;
        int orow = blockIdx.x * ROWS_PB + rr;
        if (orow < rows) {
            float s  = sPart[0][rr][0]     + sPart[1][rr][0];
            float q  = sPart[0][rr][1]     + sPart[1][rr][1];
            float dv = sPart[0][rr][2 + n] + sPart[1][rr][2 + n];
            float mu   = s * (1.0f / 1024.0f);
            float var  = fmaf(-mu, mu, q * (1.0f / 1024.0f));
            float rstd = __frcp_rn(__fsqrt_rn(var + 1e-5f));
            float lg   = fmaf(rstd, fmaf(-mu, sSB[n], dv), sSB[8 + n]);
            out[(size_t)orow * NL + n] = tanh4_round(lg);
        }
    }
}

extern "C" void kernel_launch(void* const* d_in, const int* in_sizes, int n_in,
                              void* d_out, int out_size)
{
    const float* x     = (const float*)d_in[0];  // [8,8192,1024]
    const float* gamma = (const float*)d_in[1];  // [1024]
    const float* beta  = (const float*)d_in[2];  // [1024]
    const float* W     = (const float*)d_in[3];  // [8,1024]
    float* out = (float*)d_out;                  // [8,8192,8]

    int rows = in_sizes[0] / D;
    int grid = (rows + ROWS_PB - 1) / ROWS_PB;
    fsq_kernel<<<grid, 256>>>(x, gamma, beta, W, out, rows);
}

// round 8
// speedup vs baseline: 2.0132x; 2.0132x over previous
#include <cuda_runtime.h>
#include <cuda_bf16.h>
#include <cstdint>

// FSQ: q = round(4*tanh( W @ LayerNorm(x) )), folded into a single pass:
//   logit_n = rstd * (dot(x, gamma*W_n) - mu * s_n) + b_n
// R8: R=3 rows/warp, f32x2 dot accumulators (48 regs), full LDG.128
// double-buffer prefetch. ~105 regs -> scheduling slack under the 128 cap
// (R5 failed at exactly 128). All memory ops 128-bit (R7 lesson).
// W' in smem as ulonglong2 (one level x 4 K-values), stride 9 -> conflict-free.

typedef unsigned long long u64;

__device__ __forceinline__ void fma2(u64 &d, u64 a, u64 b) {
    asm("fma.rn.f32x2 %0, %1, %2, %0;" : "+l"(d) : "l"(a), "l"(b));
}
__device__ __forceinline__ void add2(u64 &d, u64 a) {
    asm("add.rn.f32x2 %0, %0, %1;" : "+l"(d) : "l"(a));
}
__device__ __forceinline__ u64 pack2(float a, float b) {
    u64 r;
    asm("mov.b64 %0, {%1, %2};" : "=l"(r) : "r"(__float_as_uint(a)), "r"(__float_as_uint(b)));
    return r;
}
__device__ __forceinline__ float2 up2(u64 v) {
    unsigned a, b;
    asm("mov.b64 {%0, %1}, %2;" : "=r"(a), "=r"(b) : "l"(v));
    return make_float2(__uint_as_float(a), __uint_as_float(b));
}
__device__ __forceinline__ float pairsum(u64 v) {
    float2 f = up2(v);
    return f.x + f.y;
}

// rintf(4*tanh(x)), fast-math-proof (fmaf/rcp.rn/sqrt.rn only).
__device__ __forceinline__ float tanh4_round(float x) {
    float ax = fabsf(x);
    float r;
    if (ax >= 1.5f) {
        r = 4.0f;   // 4*tanh(1.5)=3.6206 -> 4; monotone beyond
    } else {
        const float T2L = 2.8853900817779268f;   // 2*log2(e)
        float t = ax * T2L;
        float k = rintf(t);
        float f = t - k;
        float y = f * 0.6931471805599453f;
        float p = 1.9841269841e-4f;
        p = fmaf(p, y, 1.3888888888e-3f);
        p = fmaf(p, y, 8.3333333333e-3f);
        p = fmaf(p, y, 4.1666666667e-2f);
        p = fmaf(p, y, 1.6666666667e-1f);
        p = fmaf(p, y, 0.5f);
        p = fmaf(p, y, 1.0f);
        p = fmaf(p, y, 1.0f);
        float scale = __int_as_float(((int)k + 127) << 23);
        float e = p * scale;                     // exp(2*ax)
        float th = (e - 1.0f) * __frcp_rn(e + 1.0f);
        r = rintf(4.0f * th);
    }
    return copysignf(r, x);
}

static const int D       = 1024;
static const int F4      = 256;   // 16B chunks per row
static const int NL      = 8;
static const int WPAD    = 9;     // ulonglong2 entries per chunk (8 + 1 pad)
static const int R       = 3;     // rows per warp
static const int ROWS_PB = 24;    // 8 warps * 3 rows

__global__ void __launch_bounds__(256, 2)
fsq_kernel(const float* __restrict__ x, const float* __restrict__ gamma,
           const float* __restrict__ beta, const float* __restrict__ W,
           float* __restrict__ out, int rows)
{
    __shared__ ulonglong2 sW[F4 * WPAD];   // 36864 B: W'[chunk][level] (2 f32x2)
    __shared__ float sStats[ROWS_PB][12];  // per-slot: sum, sumsq, 8 dots
    __shared__ float sRed[8][16];
    __shared__ float sSB[16];              // s[0..7], b[0..7]

    const int tid  = threadIdx.x;
    const int lane = tid & 31;
    const int wid  = tid >> 5;

    // ---------------- prep: W' = gamma*W into smem; s_n, b_n ----------------
    float sP[NL], bP[NL];
#pragma unroll
    for (int n = 0; n < NL; n++) { sP[n] = 0.0f; bP[n] = 0.0f; }
    {
        const float4* g4 = (const float4*)gamma;  // [256]
        const float4* e4 = (const float4*)beta;
        const float4* W4 = (const float4*)W;      // [8][256]
        int i = tid;                              // 256 threads = 256 chunks
        float4 g = g4[i];
        float4 b = e4[i];
#pragma unroll
        for (int n = 0; n < NL; n++) {
            float4 w = W4[n * F4 + i];
            float p0 = g.x * w.x, p1 = g.y * w.y, p2 = g.z * w.z, p3 = g.w * w.w;
            ulonglong2 e;
            e.x = pack2(p0, p1);
            e.y = pack2(p2, p3);
            sW[i * WPAD + n] = e;
            sP[n] += (p0 + p1) + (p2 + p3);
            bP[n] += (b.x * w.x + b.y * w.y) + (b.z * w.z + b.w * w.w);
        }
    }
#pragma unroll
    for (int o = 16; o; o >>= 1) {
#pragma unroll
        for (int n = 0; n < NL; n++) {
            sP[n] += __shfl_xor_sync(0xffffffffu, sP[n], o);
            bP[n] += __shfl_xor_sync(0xffffffffu, bP[n], o);
        }
    }
    if (lane == 0) {
#pragma unroll
        for (int n = 0; n < NL; n++) {
            sRed[wid][n]     = sP[n];
            sRed[wid][8 + n] = bP[n];
        }
    }
    __syncthreads();
    if (tid < 16) {
        float v = 0.0f;
#pragma unroll
        for (int w = 0; w < 8; w++) v += sRed[w][tid];
        sSB[tid] = v;
    }
    __syncthreads();

    // ---------------- main: 3 rows per warp, single pass ----------------
    int rowBase = blockIdx.x * ROWS_PB + wid * R;
    if (rowBase > rows - R) rowBase = rows - R;   // clamp (overlap is idempotent)
    if (rowBase < 0) rowBase = 0;
    const ulonglong2* bp = (const ulonglong2*)x + (size_t)rowBase * F4 + lane;

    u64 dots[R][NL];
    u64 sum2[R], ssq2[R];
#pragma unroll
    for (int r = 0; r < R; r++) {
        sum2[r] = 0ull; ssq2[r] = 0ull;
#pragma unroll
        for (int n = 0; n < NL; n++) dots[r][n] = 0ull;
    }

    ulonglong2 c[R];
#pragma unroll
    for (int r = 0; r < R; r++) c[r] = __ldcs(bp + r * F4);

#pragma unroll
    for (int s = 0; s < 8; s++) {
        ulonglong2 nx[R];
        if (s < 7) {
#pragma unroll
            for (int r = 0; r < R; r++)
                nx[r] = __ldcs(bp + r * F4 + (s + 1) * 32);
        }
        // stats (f32x2)
#pragma unroll
        for (int r = 0; r < R; r++) {
            add2(sum2[r], c[r].x); add2(sum2[r], c[r].y);
            fma2(ssq2[r], c[r].x, c[r].x);
            fma2(ssq2[r], c[r].y, c[r].y);
        }
        // dots (f32x2, W entry read once, serves 3 rows)
        const ulonglong2* wrow = &sW[(s * 32 + lane) * WPAD];
#pragma unroll
        for (int n = 0; n < NL; n++) {
            ulonglong2 w = wrow[n];
#pragma unroll
            for (int r = 0; r < R; r++) {
                fma2(dots[r][n], c[r].x, w.x);
                fma2(dots[r][n], c[r].y, w.y);
            }
        }
#pragma unroll
        for (int r = 0; r < R; r++) c[r] = nx[r];
    }

    // ---------------- reduce + stash stats ----------------
#pragma unroll
    for (int r = 0; r < R; r++) {
        float s = pairsum(sum2[r]);
        float q = pairsum(ssq2[r]);
        float dv[NL];
#pragma unroll
        for (int n = 0; n < NL; n++) dv[n] = pairsum(dots[r][n]);
#pragma unroll
        for (int o = 16; o; o >>= 1) {
            s += __shfl_xor_sync(0xffffffffu, s, o);
            q += __shfl_xor_sync(0xffffffffu, q, o);
#pragma unroll
            for (int n = 0; n < NL; n++)
                dv[n] += __shfl_xor_sync(0xffffffffu, dv[n], o);
        }
        if (lane == 0) {
            sStats[wid * R + r][0] = s;
            sStats[wid * R + r][1] = q;
#pragma unroll
            for (int n = 0; n < NL; n++) sStats[wid * R + r][2 + n] = dv[n];
        }
    }
    __syncthreads();

    // ---------------- tail: 192 threads = 24 slots x 8 levels ----------------
    if (tid < ROWS_PB * NL) {
        int rr = tid >> 3;                 // slot 0..23
        int n  = tid & 7;
        // recompute the same clamped row this slot's warp used
        int rb = blockIdx.x * ROWS_PB + (rr / R) * R;
        if (rb > rows - R) rb = rows - R;
        if (rb < 0) rb = 0;
        int orow = rb + (rr % R);
        float s  = sStats[rr][0];
        float q  = sStats[rr][1];
        float dv = sStats[rr][2 + n];
        float mu   = s * (1.0f / 1024.0f);
        float var  = fmaf(-mu, mu, q * (1.0f / 1024.0f));
        float rstd = __frcp_rn(__fsqrt_rn(var + 1e-5f));
        float lg   = fmaf(rstd, fmaf(-mu, sSB[n], dv), sSB[8 + n]);
        out[(size_t)orow * NL + n] = tanh4_round(lg);
    }
}

extern "C" void kernel_launch(void* const* d_in, const int* in_sizes, int n_in,
                              void* d_out, int out_size)
{
    const float* x     = (const float*)d_in[0];  // [8,8192,1024]
    const float* gamma = (const float*)d_in[1];  // [1024]
    const float* beta  = (const float*)d_in[2];  // [1024]
    const float* W     = (const float*)d_in[3];  // [8,1024]
    float* out = (float*)d_out;                  // [8,8192,8]

    int rows = in_sizes[0] / D;
    int grid = (rows + ROWS_PB - 1) / ROWS_PB;
    fsq_kernel<<<grid, 256>>>(x, gamma, beta, W, out, rows);
}